// round 1
// baseline (speedup 1.0000x reference)
#include <cuda_runtime.h>
#include <math.h>

#define DIM   1024
#define BATCH 2
#define NSEQ  2048
#define HEADS 16
#define HD    64
#define TOKENS (BATCH * NSEQ)   // 4096
#define C3    (3 * DIM)         // 3072

// Scratch (no allocations allowed): 16 + 48 + 16 MB
__device__ float g_ln[TOKENS * DIM];
__device__ float g_qkv[TOKENS * C3];
__device__ float g_attn[TOKENS * DIM];

// ---------------------------------------------------------------------------
// LayerNorm: one block per token, 256 threads, float4
// ---------------------------------------------------------------------------
__global__ __launch_bounds__(256) void ln_kernel(const float* __restrict__ x,
                                                 const float* __restrict__ gamma,
                                                 const float* __restrict__ beta) {
    int row = blockIdx.x;
    int t = threadIdx.x;
    const float4* xr = (const float4*)(x + (size_t)row * DIM);
    float4 v = xr[t];

    float s  = v.x + v.y + v.z + v.w;
    float ss = v.x*v.x + v.y*v.y + v.z*v.z + v.w*v.w;
    #pragma unroll
    for (int o = 16; o > 0; o >>= 1) {
        s  += __shfl_xor_sync(0xFFFFFFFFu, s,  o);
        ss += __shfl_xor_sync(0xFFFFFFFFu, ss, o);
    }
    __shared__ float rs[8], rss[8];
    int w = t >> 5;
    if ((t & 31) == 0) { rs[w] = s; rss[w] = ss; }
    __syncthreads();
    s = 0.f; ss = 0.f;
    #pragma unroll
    for (int i = 0; i < 8; i++) { s += rs[i]; ss += rss[i]; }

    const float invD = 1.0f / DIM;
    float mean = s * invD;
    float var  = ss * invD - mean * mean;
    float rstd = rsqrtf(var + 1e-5f);

    float4 g  = ((const float4*)gamma)[t];
    float4 be = ((const float4*)beta)[t];
    float4 o;
    o.x = (v.x - mean) * rstd * g.x + be.x;
    o.y = (v.y - mean) * rstd * g.y + be.y;
    o.z = (v.z - mean) * rstd * g.z + be.z;
    o.w = (v.w - mean) * rstd * g.w + be.w;
    ((float4*)(g_ln + (size_t)row * DIM))[t] = o;
}

// ---------------------------------------------------------------------------
// SGEMM: C[M,N] = A[M,K] @ B[K,N]  (+ bias + residual in epilogue)
// 128x128 block tile, BK=8, 256 threads, 8x8 per thread.
// M,N multiples of 128; K multiple of 8 (true for all calls here).
// ---------------------------------------------------------------------------
__global__ __launch_bounds__(256) void sgemm_kernel(
    int M, int N, int K,
    const float* __restrict__ A, const float* __restrict__ Bm, float* __restrict__ C,
    const float* __restrict__ bias, const float* __restrict__ resid) {

    __shared__ float As[8][128];
    __shared__ float Bs[8][128];

    int tid  = threadIdx.x;
    int crow = blockIdx.y * 128;
    int ccol = blockIdx.x * 128;

    int aRow = tid >> 1;          // 0..127
    int aCol = (tid & 1) * 4;     // 0 or 4
    int bRow = tid >> 5;          // 0..7
    int bCol = (tid & 31) * 4;    // 0..124

    const float* Ap = A + (size_t)(crow + aRow) * K + aCol;
    const float* Bp = Bm + (size_t)bRow * N + ccol + bCol;

    int tr = (tid >> 4) * 8;      // 0..120
    int tc = (tid & 15) * 8;      // 0..120

    float acc[8][8];
    #pragma unroll
    for (int i = 0; i < 8; i++)
        #pragma unroll
        for (int j = 0; j < 8; j++) acc[i][j] = 0.f;

    for (int k0 = 0; k0 < K; k0 += 8) {
        float4 a4 = *(const float4*)(Ap + k0);
        float4 b4 = *(const float4*)(Bp + (size_t)k0 * N);
        As[aCol + 0][aRow] = a4.x;
        As[aCol + 1][aRow] = a4.y;
        As[aCol + 2][aRow] = a4.z;
        As[aCol + 3][aRow] = a4.w;
        *(float4*)&Bs[bRow][bCol] = b4;
        __syncthreads();

        #pragma unroll
        for (int k = 0; k < 8; k++) {
            float regM[8], regN[8];
            *(float4*)&regM[0] = *(const float4*)&As[k][tr];
            *(float4*)&regM[4] = *(const float4*)&As[k][tr + 4];
            *(float4*)&regN[0] = *(const float4*)&Bs[k][tc];
            *(float4*)&regN[4] = *(const float4*)&Bs[k][tc + 4];
            #pragma unroll
            for (int i = 0; i < 8; i++)
                #pragma unroll
                for (int j = 0; j < 8; j++)
                    acc[i][j] += regM[i] * regN[j];
        }
        __syncthreads();
    }

    #pragma unroll
    for (int i = 0; i < 8; i++) {
        int r = crow + tr + i;
        #pragma unroll
        for (int j = 0; j < 8; j += 4) {
            int c = ccol + tc + j;
            float4 o = { acc[i][j], acc[i][j+1], acc[i][j+2], acc[i][j+3] };
            if (bias) {
                o.x += bias[c];   o.y += bias[c+1];
                o.z += bias[c+2]; o.w += bias[c+3];
            }
            if (resid) {
                float4 rr = *(const float4*)(resid + (size_t)r * N + c);
                o.x += rr.x; o.y += rr.y; o.z += rr.z; o.w += rr.w;
            }
            *(float4*)(C + (size_t)r * N + c) = o;
        }
    }
}

// ---------------------------------------------------------------------------
// Flash attention: block = 128 queries of one (b,h); 128 threads, each owns
// one query row. K/V tiles 32x64 in smem (broadcast reads). Online softmax
// with scores held in registers, per-tile rescale.
// ---------------------------------------------------------------------------
#define BK 32

__global__ __launch_bounds__(128) void attn_kernel() {
    __shared__ float sK[BK * HD];
    __shared__ float sV[BK * HD];

    int bh = blockIdx.y;
    int b = bh >> 4, h = bh & 15;
    int q0 = blockIdx.x * 128;
    int tid = threadIdx.x;

    const float* qp = g_qkv + (size_t)(b * NSEQ + q0 + tid) * C3 + h * HD;
    float4 q[16];
    #pragma unroll
    for (int i = 0; i < 16; i++) q[i] = ((const float4*)qp)[i];

    float acc[HD];
    #pragma unroll
    for (int d = 0; d < HD; d++) acc[d] = 0.f;
    float m = -1e30f, l = 0.f;

    int r  = tid >> 2;           // 0..31
    int c0 = (tid & 3) * 16;     // 0,16,32,48

    for (int k0 = 0; k0 < NSEQ; k0 += BK) {
        __syncthreads();
        const float* kp = g_qkv + (size_t)(b * NSEQ + k0 + r) * C3 + DIM + h * HD + c0;
        #pragma unroll
        for (int i = 0; i < 4; i++) {
            ((float4*)(sK + r * HD + c0))[i] = ((const float4*)kp)[i];
            ((float4*)(sV + r * HD + c0))[i] = ((const float4*)(kp + DIM))[i];
        }
        __syncthreads();

        float s[BK];
        float tmax = -1e30f;
        #pragma unroll
        for (int j = 0; j < BK; j++) {
            const float4* k4 = (const float4*)(sK + j * HD);
            float d0 = 0.f;
            #pragma unroll
            for (int i = 0; i < 16; i++) {
                float4 kk = k4[i];
                d0 += q[i].x * kk.x; d0 += q[i].y * kk.y;
                d0 += q[i].z * kk.z; d0 += q[i].w * kk.w;
            }
            s[j] = d0 * 0.125f;   // 1/sqrt(64)
            tmax = fmaxf(tmax, s[j]);
        }

        float mnew = fmaxf(m, tmax);
        float corr = __expf(m - mnew);
        l *= corr;
        #pragma unroll
        for (int d = 0; d < HD; d++) acc[d] *= corr;
        m = mnew;

        #pragma unroll
        for (int j = 0; j < BK; j++) {
            float p = __expf(s[j] - m);
            l += p;
            const float4* v4 = (const float4*)(sV + j * HD);
            #pragma unroll
            for (int i = 0; i < 16; i++) {
                float4 vv = v4[i];
                acc[4*i+0] += p * vv.x; acc[4*i+1] += p * vv.y;
                acc[4*i+2] += p * vv.z; acc[4*i+3] += p * vv.w;
            }
        }
    }

    float inv = 1.0f / l;
    float* op = g_attn + (size_t)(b * NSEQ + q0 + tid) * DIM + h * HD;
    #pragma unroll
    for (int i = 0; i < 16; i++) {
        float4 o = { acc[4*i] * inv, acc[4*i+1] * inv, acc[4*i+2] * inv, acc[4*i+3] * inv };
        ((float4*)op)[i] = o;
    }
}

// ---------------------------------------------------------------------------
extern "C" void kernel_launch(void* const* d_in, const int* in_sizes, int n_in,
                              void* d_out, int out_size) {
    const float* x      = (const float*)d_in[0];
    const float* w_qkv  = (const float*)d_in[1];
    const float* w_proj = (const float*)d_in[2];
    const float* b_proj = (const float*)d_in[3];
    const float* gamma  = (const float*)d_in[4];
    const float* beta   = (const float*)d_in[5];
    float* out = (float*)d_out;

    float *ln_p, *qkv_p, *attn_p;
    cudaGetSymbolAddress((void**)&ln_p,   g_ln);
    cudaGetSymbolAddress((void**)&qkv_p,  g_qkv);
    cudaGetSymbolAddress((void**)&attn_p, g_attn);

    // 1. LayerNorm
    ln_kernel<<<TOKENS, 256>>>(x, gamma, beta);

    // 2. QKV GEMM: [4096,1024] @ [1024,3072]
    sgemm_kernel<<<dim3(C3 / 128, TOKENS / 128), 256>>>(
        TOKENS, C3, DIM, ln_p, w_qkv, qkv_p, nullptr, nullptr);

    // 3. Attention (writes [B,N,H,D] == [4096,1024])
    attn_kernel<<<dim3(NSEQ / 128, BATCH * HEADS), 128>>>();

    // 4. Proj GEMM + bias + residual: [4096,1024] @ [1024,1024]
    sgemm_kernel<<<dim3(DIM / 128, TOKENS / 128), 256>>>(
        TOKENS, DIM, DIM, attn_p, w_proj, out, b_proj, x);
}

// round 3
// speedup vs baseline: 4.8542x; 4.8542x over previous
#include <cuda_runtime.h>
#include <cuda_bf16.h>
#include <math.h>
#include <stdint.h>

#define DIM    1024
#define BATCH  2
#define NSEQ   2048
#define HEADS  16
#define HD     64
#define TOKENS (BATCH * NSEQ)     // 4096
#define C3     (3 * DIM)          // 3072
#define QSCALE 0.1803368801111204f   // 0.125 * log2(e)

// ---------------- scratch (__device__ globals; no allocations allowed) -----
__device__ __nv_bfloat16 g_ln_h[TOKENS * DIM];
__device__ __nv_bfloat16 g_ln_l[TOKENS * DIM];
__device__ __nv_bfloat16 g_wqkvT_h[C3 * DIM];   // [N=3072][K=1024]
__device__ __nv_bfloat16 g_wqkvT_l[C3 * DIM];
__device__ __nv_bfloat16 g_wprojT_h[DIM * DIM]; // [N=1024][K=1024]
__device__ __nv_bfloat16 g_wprojT_l[DIM * DIM];
__device__ __nv_bfloat16 g_q[BATCH * HEADS * NSEQ * HD];  // [bh][n][64], pre-scaled
__device__ __nv_bfloat16 g_k[BATCH * HEADS * NSEQ * HD];
__device__ __nv_bfloat16 g_v[BATCH * HEADS * NSEQ * HD];
__device__ __nv_bfloat16 g_attn_h[TOKENS * DIM];
__device__ __nv_bfloat16 g_attn_l[TOKENS * DIM];

// ---------------- low-level helpers ----------------------------------------
__device__ __forceinline__ uint32_t smem_u32(const void* p) {
    uint32_t a;
    asm("{ .reg .u64 t; cvta.to.shared.u64 t, %1; cvt.u32.u64 %0, t; }"
        : "=r"(a) : "l"(p));
    return a;
}
__device__ __forceinline__ uint32_t sw(uint32_t o) {   // SW128-style XOR swizzle
    return o ^ ((o >> 3) & 0x70);
}
__device__ __forceinline__ void ldsm4(uint32_t* r, uint32_t a) {
    asm volatile("ldmatrix.sync.aligned.m8n8.x4.shared.b16 {%0,%1,%2,%3}, [%4];"
                 : "=r"(r[0]), "=r"(r[1]), "=r"(r[2]), "=r"(r[3]) : "r"(a));
}
__device__ __forceinline__ void ldsm4t(uint32_t* r, uint32_t a) {
    asm volatile("ldmatrix.sync.aligned.m8n8.x4.trans.shared.b16 {%0,%1,%2,%3}, [%4];"
                 : "=r"(r[0]), "=r"(r[1]), "=r"(r[2]), "=r"(r[3]) : "r"(a));
}
__device__ __forceinline__ void mma16816(float* c, const uint32_t* a,
                                         uint32_t b0, uint32_t b1) {
    asm volatile(
        "mma.sync.aligned.m16n8k16.row.col.f32.bf16.bf16.f32 "
        "{%0,%1,%2,%3}, {%4,%5,%6,%7}, {%8,%9}, {%0,%1,%2,%3};"
        : "+f"(c[0]), "+f"(c[1]), "+f"(c[2]), "+f"(c[3])
        : "r"(a[0]), "r"(a[1]), "r"(a[2]), "r"(a[3]), "r"(b0), "r"(b1));
}
#define CP16(dst, src) \
    asm volatile("cp.async.cg.shared.global [%0], [%1], 16;" :: "r"(dst), "l"(src))
#define CP_COMMIT() asm volatile("cp.async.commit_group;" ::: "memory")
#define CP_WAIT1()  asm volatile("cp.async.wait_group 1;" ::: "memory")
#define CP_WAIT0()  asm volatile("cp.async.wait_group 0;" ::: "memory")

__device__ __forceinline__ float ex2(float x) {
    float y;
    asm("ex2.approx.ftz.f32 %0, %1;" : "=f"(y) : "f"(x));
    return y;
}
__device__ __forceinline__ uint32_t pack_bf16(float lo, float hi) {
    uint32_t r;
    asm("cvt.rn.bf16x2.f32 %0, %1, %2;" : "=r"(r) : "f"(hi), "f"(lo));
    return r;
}
__device__ __forceinline__ void split_store(float f0, float f1,
                                            __nv_bfloat16* H, __nv_bfloat16* L) {
    __nv_bfloat16 h0 = __float2bfloat16(f0);
    __nv_bfloat16 h1 = __float2bfloat16(f1);
    float r0 = f0 - __bfloat162float(h0);
    float r1 = f1 - __bfloat162float(h1);
    *(uint32_t*)H = pack_bf16(__bfloat162float(h0), __bfloat162float(h1));
    *(uint32_t*)L = pack_bf16(r0, r1);
}

// ---------------------------------------------------------------------------
// LayerNorm -> bf16 hi/lo
// ---------------------------------------------------------------------------
__global__ __launch_bounds__(256) void ln_kernel(const float* __restrict__ x,
                                                 const float* __restrict__ gamma,
                                                 const float* __restrict__ beta) {
    int row = blockIdx.x;
    int t = threadIdx.x;
    const float4* xr = (const float4*)(x + (size_t)row * DIM);
    float4 v = xr[t];

    float s  = v.x + v.y + v.z + v.w;
    float ss = v.x*v.x + v.y*v.y + v.z*v.z + v.w*v.w;
    #pragma unroll
    for (int o = 16; o > 0; o >>= 1) {
        s  += __shfl_xor_sync(0xFFFFFFFFu, s,  o);
        ss += __shfl_xor_sync(0xFFFFFFFFu, ss, o);
    }
    __shared__ float rs[8], rss[8];
    int w = t >> 5;
    if ((t & 31) == 0) { rs[w] = s; rss[w] = ss; }
    __syncthreads();
    s = 0.f; ss = 0.f;
    #pragma unroll
    for (int i = 0; i < 8; i++) { s += rs[i]; ss += rss[i]; }

    const float invD = 1.0f / DIM;
    float mean = s * invD;
    float var  = ss * invD - mean * mean;
    float rstd = rsqrtf(var + 1e-5f);

    float4 g  = ((const float4*)gamma)[t];
    float4 be = ((const float4*)beta)[t];
    float o0 = (v.x - mean) * rstd * g.x + be.x;
    float o1 = (v.y - mean) * rstd * g.y + be.y;
    float o2 = (v.z - mean) * rstd * g.z + be.z;
    float o3 = (v.w - mean) * rstd * g.w + be.w;

    size_t idx = (size_t)row * DIM + t * 4;
    split_store(o0, o1, g_ln_h + idx,     g_ln_l + idx);
    split_store(o2, o3, g_ln_h + idx + 2, g_ln_l + idx + 2);
}

// ---------------------------------------------------------------------------
// Weight split + transpose: W[K,N] fp32 -> hi/lo bf16 [N,K]
// ---------------------------------------------------------------------------
__global__ __launch_bounds__(256) void split_transpose(
    const float* __restrict__ W, __nv_bfloat16* __restrict__ Th,
    __nv_bfloat16* __restrict__ Tl, int K, int N) {
    __shared__ float tile[32][33];
    int n0 = blockIdx.x * 32, k0 = blockIdx.y * 32;
    int tx = threadIdx.x, ty = threadIdx.y;
    #pragma unroll
    for (int r = ty; r < 32; r += 8)
        tile[r][tx] = W[(size_t)(k0 + r) * N + n0 + tx];
    __syncthreads();
    #pragma unroll
    for (int r = ty; r < 32; r += 8) {
        float v = tile[tx][r];   // = W[k0+tx][n0+r]
        __nv_bfloat16 h = __float2bfloat16(v);
        size_t idx = (size_t)(n0 + r) * K + k0 + tx;
        Th[idx] = h;
        Tl[idx] = __float2bfloat16(v - __bfloat162float(h));
    }
}

// ---------------------------------------------------------------------------
// GEMM on mma.sync (bf16 hi/lo 3-term): C[M,N] = A[M,1024] @ B[N,1024]^T
// CTA 128x128, 8 warps (4Mx2N, warp tile 32x64), K-chunk 32, cp.async x2 buf.
// MODE 0: epilogue scatters to g_q/g_k/g_v bf16 (Q pre-scaled).
// MODE 1: epilogue += bias + resid, fp32 out (N=1024).
// Smem stage (32KB): Ah@0 Al@8K Bh@16K Bl@24K; two stages = 64KB.
// ---------------------------------------------------------------------------
#define GSMEM (2 * 32768)

__device__ __forceinline__ void gemm_load_stage(
    const __nv_bfloat16* Ah, const __nv_bfloat16* Al,
    const __nv_bfloat16* Bh, const __nv_bfloat16* Bl,
    int crow, int ccol, int ch, uint32_t sbase, int tid) {
    #pragma unroll
    for (int half = 0; half < 2; half++) {
        int i = tid + half * 256;
        int row = i >> 2, kc = i & 3;
        uint32_t d = sbase + sw((uint32_t)(row * 64 + kc * 16));
        size_t ga = (size_t)(crow + row) * DIM + ch * 32 + kc * 8;
        size_t gb = (size_t)(ccol + row) * DIM + ch * 32 + kc * 8;
        CP16(d,         Ah + ga);
        CP16(d + 8192,  Al + ga);
        CP16(d + 16384, Bh + gb);
        CP16(d + 24576, Bl + gb);
    }
}

template <int MODE>
__global__ __launch_bounds__(256) void gemm_mma(
    const __nv_bfloat16* __restrict__ Ah, const __nv_bfloat16* __restrict__ Al,
    const __nv_bfloat16* __restrict__ Bh, const __nv_bfloat16* __restrict__ Bl,
    float* __restrict__ out, const float* __restrict__ bias,
    const float* __restrict__ resid) {

    extern __shared__ char smc[];
    uint32_t smb = smem_u32(smc);
    int tid = threadIdx.x, wid = tid >> 5, lane = tid & 31;
    int wm = wid & 3, wn = wid >> 2;
    int crow = blockIdx.y * 128, ccol = blockIdx.x * 128;

    float acc[2][8][4];
    #pragma unroll
    for (int a = 0; a < 2; a++)
        #pragma unroll
        for (int b = 0; b < 8; b++)
            #pragma unroll
            for (int c = 0; c < 4; c++) acc[a][b][c] = 0.f;

    gemm_load_stage(Ah, Al, Bh, Bl, crow, ccol, 0, smb, tid);
    CP_COMMIT();

    for (int ch = 0; ch < 32; ch++) {
        int s = ch & 1;
        if (ch < 31) {
            gemm_load_stage(Ah, Al, Bh, Bl, crow, ccol, ch + 1,
                            smb + (s ^ 1) * 32768, tid);
            CP_COMMIT();
            CP_WAIT1();
        } else {
            CP_WAIT0();
        }
        __syncthreads();

        uint32_t Abase = smb + s * 32768;
        uint32_t Bbase = Abase + 16384;

        #pragma unroll
        for (int kt = 0; kt < 2; kt++) {
            uint32_t ah[2][4], al[2][4];
            #pragma unroll
            for (int mt = 0; mt < 2; mt++) {
                uint32_t off = Abase + sw((uint32_t)(
                    (wm * 32 + mt * 16 + (lane & 15)) * 64 +
                    kt * 32 + (lane >> 4) * 16));
                ldsm4(ah[mt], off);
                ldsm4(al[mt], off + 8192);
            }
            #pragma unroll
            for (int jp = 0; jp < 4; jp++) {
                uint32_t boff = Bbase + sw((uint32_t)(
                    (wn * 64 + jp * 16 + (lane >> 4) * 8 + (lane & 7)) * 64 +
                    kt * 32 + ((lane >> 3) & 1) * 16));
                uint32_t bh[4], bl[4];
                ldsm4(bh, boff);
                ldsm4(bl, boff + 8192);
                #pragma unroll
                for (int mt = 0; mt < 2; mt++) {
                    mma16816(acc[mt][2*jp],   ah[mt], bh[0], bh[1]);
                    mma16816(acc[mt][2*jp+1], ah[mt], bh[2], bh[3]);
                    mma16816(acc[mt][2*jp],   ah[mt], bl[0], bl[1]);
                    mma16816(acc[mt][2*jp+1], ah[mt], bl[2], bl[3]);
                    mma16816(acc[mt][2*jp],   al[mt], bh[0], bh[1]);
                    mma16816(acc[mt][2*jp+1], al[mt], bh[2], bh[3]);
                }
            }
        }
        __syncthreads();
    }

    // epilogue
    int g = lane >> 2, t2 = (lane & 3) * 2;
    #pragma unroll
    for (int mt = 0; mt < 2; mt++) {
        int row0 = crow + wm * 32 + mt * 16 + g;
        #pragma unroll
        for (int j = 0; j < 8; j++) {
            int col = ccol + wn * 64 + j * 8 + t2;
            if (MODE == 0) {
                // scatter to q/k/v [bh][n][64]
                #pragma unroll
                for (int r = 0; r < 2; r++) {
                    int tok = row0 + r * 8;
                    float v0 = acc[mt][j][2*r], v1 = acc[mt][j][2*r+1];
                    int which = col >> 10, rem = col & 1023;
                    int h = rem >> 6, d = rem & 63;
                    __nv_bfloat16* dst = (which == 0) ? g_q : (which == 1) ? g_k : g_v;
                    float sc = (which == 0) ? QSCALE : 1.f;
                    size_t off = ((size_t)((tok >> 11) * HEADS + h) * NSEQ +
                                  (tok & (NSEQ - 1))) * HD + d;
                    *(uint32_t*)(dst + off) = pack_bf16(v0 * sc, v1 * sc);
                }
            } else {
                float b0 = bias[col], b1 = bias[col + 1];
                #pragma unroll
                for (int r = 0; r < 2; r++) {
                    size_t o = (size_t)(row0 + r * 8) * DIM + col;
                    float2 rr = *(const float2*)(resid + o);
                    float2 vv = { acc[mt][j][2*r] + b0 + rr.x,
                                  acc[mt][j][2*r+1] + b1 + rr.y };
                    *(float2*)(out + o) = vv;
                }
            }
        }
    }
}

// ---------------------------------------------------------------------------
// Flash attention on mma.sync (raw bf16). CTA = 128 q x one (b,h); 8 warps.
// Smem: Q 16KB @0; stages: K@16384+s*16384, V = K+8192. Total 49152.
// ---------------------------------------------------------------------------
#define ASMEM 49152

__device__ __forceinline__ void kv_load_stage(
    const __nv_bfloat16* kg, const __nv_bfloat16* vg, int k0,
    uint32_t sbase, int tid) {
    #pragma unroll
    for (int half = 0; half < 2; half++) {
        int i = tid + half * 256;
        int key = i >> 3, ck = i & 7;
        uint32_t d = sbase + sw((uint32_t)(key * 128 + ck * 16));
        size_t gsrc = (size_t)(k0 + key) * HD + ck * 8;
        CP16(d,        kg + gsrc);
        CP16(d + 8192, vg + gsrc);
    }
}

__global__ __launch_bounds__(256) void attn_mma() {
    extern __shared__ char smc[];
    uint32_t smb = smem_u32(smc);
    int tid = threadIdx.x, wid = tid >> 5, lane = tid & 31;
    int bh = blockIdx.y;
    int q0 = blockIdx.x * 128;

    const __nv_bfloat16* qg = g_q + (size_t)bh * NSEQ * HD;
    const __nv_bfloat16* kg = g_k + (size_t)bh * NSEQ * HD;
    const __nv_bfloat16* vg = g_v + (size_t)bh * NSEQ * HD;

    // stage Q (128x64 bf16, swizzled)
    #pragma unroll
    for (int it = 0; it < 4; it++) {
        int i = tid * 4 + it;
        int row = i >> 3, ck = i & 7;
        uint4 val = *(const uint4*)(qg + (size_t)(q0 + row) * HD + ck * 8);
        *(uint4*)(smc + sw((uint32_t)(row * 128 + ck * 16))) = val;
    }
    __syncthreads();

    uint32_t qa[4][4];
    #pragma unroll
    for (int kt = 0; kt < 4; kt++) {
        uint32_t off = smb + sw((uint32_t)(
            (wid * 16 + (lane & 15)) * 128 + kt * 32 + (lane >> 4) * 16));
        ldsm4(qa[kt], off);
    }

    float o[8][4];
    #pragma unroll
    for (int j = 0; j < 8; j++)
        #pragma unroll
        for (int c = 0; c < 4; c++) o[j][c] = 0.f;
    float m0 = -1e30f, m1 = -1e30f, l0 = 0.f, l1 = 0.f;

    kv_load_stage(kg, vg, 0, smb + 16384, tid);
    CP_COMMIT();

    for (int t = 0; t < NSEQ / 64; t++) {
        int s = t & 1;
        if (t < NSEQ / 64 - 1) {
            kv_load_stage(kg, vg, (t + 1) * 64, smb + 16384 + (s ^ 1) * 16384, tid);
            CP_COMMIT();
            CP_WAIT1();
        } else {
            CP_WAIT0();
        }
        __syncthreads();

        uint32_t Kb = smb + 16384 + s * 16384;
        uint32_t Vb = Kb + 8192;

        // S = Q K^T
        float sc[8][4];
        #pragma unroll
        for (int j = 0; j < 8; j++)
            #pragma unroll
            for (int c = 0; c < 4; c++) sc[j][c] = 0.f;

        #pragma unroll
        for (int kt = 0; kt < 4; kt++) {
            #pragma unroll
            for (int jp = 0; jp < 4; jp++) {
                uint32_t r[4];
                uint32_t off = Kb + sw((uint32_t)(
                    (jp * 16 + (lane >> 4) * 8 + (lane & 7)) * 128 +
                    kt * 32 + ((lane >> 3) & 1) * 16));
                ldsm4(r, off);
                mma16816(sc[2*jp],   qa[kt], r[0], r[1]);
                mma16816(sc[2*jp+1], qa[kt], r[2], r[3]);
            }
        }

        // online softmax (log2 domain: Q pre-scaled by 0.125*log2e)
        float mx0 = -1e30f, mx1 = -1e30f;
        #pragma unroll
        for (int j = 0; j < 8; j++) {
            mx0 = fmaxf(mx0, fmaxf(sc[j][0], sc[j][1]));
            mx1 = fmaxf(mx1, fmaxf(sc[j][2], sc[j][3]));
        }
        mx0 = fmaxf(mx0, __shfl_xor_sync(0xFFFFFFFFu, mx0, 1));
        mx0 = fmaxf(mx0, __shfl_xor_sync(0xFFFFFFFFu, mx0, 2));
        mx1 = fmaxf(mx1, __shfl_xor_sync(0xFFFFFFFFu, mx1, 1));
        mx1 = fmaxf(mx1, __shfl_xor_sync(0xFFFFFFFFu, mx1, 2));
        float mn0 = fmaxf(m0, mx0), mn1 = fmaxf(m1, mx1);
        float cr0 = ex2(m0 - mn0), cr1 = ex2(m1 - mn1);
        m0 = mn0; m1 = mn1;

        uint32_t pa[4][4];
        float sl0 = 0.f, sl1 = 0.f;
        #pragma unroll
        for (int j = 0; j < 8; j++) {
            float p0 = ex2(sc[j][0] - mn0), p1 = ex2(sc[j][1] - mn0);
            float p2 = ex2(sc[j][2] - mn1), p3 = ex2(sc[j][3] - mn1);
            sl0 += p0 + p1; sl1 += p2 + p3;
            int kt = j >> 1, hi = (j & 1) * 2;
            pa[kt][hi]     = pack_bf16(p0, p1);
            pa[kt][hi + 1] = pack_bf16(p2, p3);
        }
        l0 = l0 * cr0 + sl0;
        l1 = l1 * cr1 + sl1;
        #pragma unroll
        for (int j = 0; j < 8; j++) {
            o[j][0] *= cr0; o[j][1] *= cr0;
            o[j][2] *= cr1; o[j][3] *= cr1;
        }

        // O += P V
        #pragma unroll
        for (int kt = 0; kt < 4; kt++) {
            #pragma unroll
            for (int j2 = 0; j2 < 4; j2++) {
                uint32_t v[4];
                uint32_t off = Vb + sw((uint32_t)(
                    (kt * 16 + ((lane >> 3) & 1) * 8 + (lane & 7)) * 128 +
                    j2 * 32 + ((lane >> 4) & 1) * 16));
                ldsm4t(v, off);
                mma16816(o[2*j2],   pa[kt], v[0], v[1]);
                mma16816(o[2*j2+1], pa[kt], v[2], v[3]);
            }
        }
        __syncthreads();
    }

    // epilogue
    l0 += __shfl_xor_sync(0xFFFFFFFFu, l0, 1);
    l0 += __shfl_xor_sync(0xFFFFFFFFu, l0, 2);
    l1 += __shfl_xor_sync(0xFFFFFFFFu, l1, 1);
    l1 += __shfl_xor_sync(0xFFFFFFFFu, l1, 2);
    float inv0 = 1.f / l0, inv1 = 1.f / l1;

    int b = bh >> 4, h = bh & 15;
    int n0 = q0 + wid * 16 + (lane >> 2);
    size_t t0 = (size_t)(b * NSEQ + n0) * DIM + h * HD;
    size_t t1 = t0 + (size_t)8 * DIM;
    #pragma unroll
    for (int j = 0; j < 8; j++) {
        int d = j * 8 + (lane & 3) * 2;
        split_store(o[j][0] * inv0, o[j][1] * inv0, g_attn_h + t0 + d, g_attn_l + t0 + d);
        split_store(o[j][2] * inv1, o[j][3] * inv1, g_attn_h + t1 + d, g_attn_l + t1 + d);
    }
}

// ---------------------------------------------------------------------------
extern "C" void kernel_launch(void* const* d_in, const int* in_sizes, int n_in,
                              void* d_out, int out_size) {
    const float* x      = (const float*)d_in[0];
    const float* w_qkv  = (const float*)d_in[1];
    const float* w_proj = (const float*)d_in[2];
    const float* b_proj = (const float*)d_in[3];
    const float* gamma  = (const float*)d_in[4];
    const float* beta   = (const float*)d_in[5];
    float* out = (float*)d_out;

    cudaFuncSetAttribute(gemm_mma<0>, cudaFuncAttributeMaxDynamicSharedMemorySize, GSMEM);
    cudaFuncSetAttribute(gemm_mma<1>, cudaFuncAttributeMaxDynamicSharedMemorySize, GSMEM);
    cudaFuncSetAttribute(attn_mma,    cudaFuncAttributeMaxDynamicSharedMemorySize, ASMEM);

    __nv_bfloat16 *lnh, *lnl, *wqh, *wql, *wph, *wpl, *ath, *atl;
    cudaGetSymbolAddress((void**)&lnh, g_ln_h);
    cudaGetSymbolAddress((void**)&lnl, g_ln_l);
    cudaGetSymbolAddress((void**)&wqh, g_wqkvT_h);
    cudaGetSymbolAddress((void**)&wql, g_wqkvT_l);
    cudaGetSymbolAddress((void**)&wph, g_wprojT_h);
    cudaGetSymbolAddress((void**)&wpl, g_wprojT_l);
    cudaGetSymbolAddress((void**)&ath, g_attn_h);
    cudaGetSymbolAddress((void**)&atl, g_attn_l);

    // 1. LayerNorm -> bf16 hi/lo
    ln_kernel<<<TOKENS, 256>>>(x, gamma, beta);

    // 2. weight split-transpose -> [N][K] bf16 hi/lo
    split_transpose<<<dim3(C3 / 32, DIM / 32), dim3(32, 8)>>>(w_qkv, wqh, wql, DIM, C3);
    split_transpose<<<dim3(DIM / 32, DIM / 32), dim3(32, 8)>>>(w_proj, wph, wpl, DIM, DIM);

    // 3. QKV GEMM -> scatter bf16 q/k/v (q pre-scaled)
    gemm_mma<0><<<dim3(C3 / 128, TOKENS / 128), 256, GSMEM>>>(
        lnh, lnl, wqh, wql, nullptr, nullptr, nullptr);

    // 4. attention -> bf16 hi/lo [token][1024]
    attn_mma<<<dim3(NSEQ / 128, BATCH * HEADS), 256, ASMEM>>>();

    // 5. proj GEMM + bias + residual -> d_out
    gemm_mma<1><<<dim3(DIM / 128, TOKENS / 128), 256, GSMEM>>>(
        ath, atl, wph, wpl, out, b_proj, x);
}

// round 4
// speedup vs baseline: 8.6671x; 1.7855x over previous
#include <cuda_runtime.h>
#include <cuda_fp16.h>
#include <math.h>
#include <stdint.h>

#define DIM    1024
#define BATCH  2
#define NSEQ   2048
#define HEADS  16
#define HD     64
#define TOKENS (BATCH * NSEQ)     // 4096
#define C3     (3 * DIM)          // 3072
#define QSCALE 0.1803368801111204f   // 0.125 * log2(e)

// ---------------- scratch (__device__ globals; no allocations allowed) -----
__device__ __half g_ln[TOKENS * DIM];
__device__ __half g_wqkvT[C3 * DIM];    // [N=3072][K=1024]
__device__ __half g_wprojT[DIM * DIM];  // [N=1024][K=1024]
__device__ __half g_q[BATCH * HEADS * NSEQ * HD];   // [bh][n][64], pre-scaled
__device__ __half g_k[BATCH * HEADS * NSEQ * HD];
__device__ __half g_v[BATCH * HEADS * NSEQ * HD];
__device__ __half g_attn[TOKENS * DIM];

// ---------------- low-level helpers ----------------------------------------
__device__ __forceinline__ uint32_t smem_u32(const void* p) {
    uint32_t a;
    asm("{ .reg .u64 t; cvta.to.shared.u64 t, %1; cvt.u32.u64 %0, t; }"
        : "=r"(a) : "l"(p));
    return a;
}
__device__ __forceinline__ uint32_t sw(uint32_t o) {   // XOR swizzle
    return o ^ ((o >> 3) & 0x70);
}
__device__ __forceinline__ void ldsm4(uint32_t* r, uint32_t a) {
    asm volatile("ldmatrix.sync.aligned.m8n8.x4.shared.b16 {%0,%1,%2,%3}, [%4];"
                 : "=r"(r[0]), "=r"(r[1]), "=r"(r[2]), "=r"(r[3]) : "r"(a));
}
__device__ __forceinline__ void ldsm4t(uint32_t* r, uint32_t a) {
    asm volatile("ldmatrix.sync.aligned.m8n8.x4.trans.shared.b16 {%0,%1,%2,%3}, [%4];"
                 : "=r"(r[0]), "=r"(r[1]), "=r"(r[2]), "=r"(r[3]) : "r"(a));
}
__device__ __forceinline__ void mma16816(float* c, const uint32_t* a,
                                         uint32_t b0, uint32_t b1) {
    asm volatile(
        "mma.sync.aligned.m16n8k16.row.col.f32.f16.f16.f32 "
        "{%0,%1,%2,%3}, {%4,%5,%6,%7}, {%8,%9}, {%0,%1,%2,%3};"
        : "+f"(c[0]), "+f"(c[1]), "+f"(c[2]), "+f"(c[3])
        : "r"(a[0]), "r"(a[1]), "r"(a[2]), "r"(a[3]), "r"(b0), "r"(b1));
}
#define CP16(dst, src) \
    asm volatile("cp.async.cg.shared.global [%0], [%1], 16;" :: "r"(dst), "l"(src))
#define CP_COMMIT() asm volatile("cp.async.commit_group;" ::: "memory")
#define CP_WAIT1()  asm volatile("cp.async.wait_group 1;" ::: "memory")
#define CP_WAIT0()  asm volatile("cp.async.wait_group 0;" ::: "memory")

__device__ __forceinline__ float ex2(float x) {
    float y;
    asm("ex2.approx.ftz.f32 %0, %1;" : "=f"(y) : "f"(x));
    return y;
}
__device__ __forceinline__ uint32_t pack_f16(float lo, float hi) {
    uint32_t r;
    asm("cvt.rn.f16x2.f32 %0, %1, %2;" : "=r"(r) : "f"(hi), "f"(lo));
    return r;
}

// ---------------------------------------------------------------------------
// LayerNorm -> fp16
// ---------------------------------------------------------------------------
__global__ __launch_bounds__(256) void ln_kernel(const float* __restrict__ x,
                                                 const float* __restrict__ gamma,
                                                 const float* __restrict__ beta) {
    int row = blockIdx.x;
    int t = threadIdx.x;
    const float4* xr = (const float4*)(x + (size_t)row * DIM);
    float4 v = xr[t];

    float s  = v.x + v.y + v.z + v.w;
    float ss = v.x*v.x + v.y*v.y + v.z*v.z + v.w*v.w;
    #pragma unroll
    for (int o = 16; o > 0; o >>= 1) {
        s  += __shfl_xor_sync(0xFFFFFFFFu, s,  o);
        ss += __shfl_xor_sync(0xFFFFFFFFu, ss, o);
    }
    __shared__ float rs[8], rss[8];
    int w = t >> 5;
    if ((t & 31) == 0) { rs[w] = s; rss[w] = ss; }
    __syncthreads();
    s = 0.f; ss = 0.f;
    #pragma unroll
    for (int i = 0; i < 8; i++) { s += rs[i]; ss += rss[i]; }

    const float invD = 1.0f / DIM;
    float mean = s * invD;
    float var  = ss * invD - mean * mean;
    float rstd = rsqrtf(var + 1e-5f);

    float4 g  = ((const float4*)gamma)[t];
    float4 be = ((const float4*)beta)[t];
    float o0 = (v.x - mean) * rstd * g.x + be.x;
    float o1 = (v.y - mean) * rstd * g.y + be.y;
    float o2 = (v.z - mean) * rstd * g.z + be.z;
    float o3 = (v.w - mean) * rstd * g.w + be.w;

    size_t idx = (size_t)row * DIM + t * 4;
    *(uint32_t*)(g_ln + idx)     = pack_f16(o0, o1);
    *(uint32_t*)(g_ln + idx + 2) = pack_f16(o2, o3);
}

// ---------------------------------------------------------------------------
// Weight transpose: W[K,N] fp32 -> fp16 [N,K]
// ---------------------------------------------------------------------------
__global__ __launch_bounds__(256) void wt_transpose(
    const float* __restrict__ W, __half* __restrict__ T, int K, int N) {
    __shared__ float tile[32][33];
    int n0 = blockIdx.x * 32, k0 = blockIdx.y * 32;
    int tx = threadIdx.x, ty = threadIdx.y;
    #pragma unroll
    for (int r = ty; r < 32; r += 8)
        tile[r][tx] = W[(size_t)(k0 + r) * N + n0 + tx];
    __syncthreads();
    #pragma unroll
    for (int r = ty; r < 32; r += 8)
        T[(size_t)(n0 + r) * K + k0 + tx] = __float2half(tile[tx][r]);
}

// ---------------------------------------------------------------------------
// GEMM on mma.sync fp16: C[M,N] = A[M,1024] @ B[N,1024]^T
// CTA 128x128, 8 warps (4Mx2N, warp tile 32x64), K-chunk 32, cp.async x2 buf.
// Stage 16KB: A@0 (8KB), B@8192 (8KB).
// MODE 0: scatter to g_q/g_k/g_v fp16 (Q pre-scaled).  MODE 1: +bias+resid.
// ---------------------------------------------------------------------------
#define GSMEM (2 * 16384)

__device__ __forceinline__ void gemm_load_stage(
    const __half* A, const __half* B, int crow, int ccol, int ch,
    uint32_t sbase, int tid) {
    #pragma unroll
    for (int half_ = 0; half_ < 2; half_++) {
        int i = tid + half_ * 256;
        int row = i >> 2, kc = i & 3;
        uint32_t d = sbase + sw((uint32_t)(row * 64 + kc * 16));
        size_t off = (size_t)row * DIM + ch * 32 + kc * 8;
        CP16(d,        A + (size_t)crow * DIM + off);
        CP16(d + 8192, B + (size_t)ccol * DIM + off);
    }
}

template <int MODE>
__global__ __launch_bounds__(256, 2) void gemm_mma(
    const __half* __restrict__ A, const __half* __restrict__ B,
    float* __restrict__ out, const float* __restrict__ bias,
    const float* __restrict__ resid) {

    extern __shared__ char smc[];
    uint32_t smb = smem_u32(smc);
    int tid = threadIdx.x, wid = tid >> 5, lane = tid & 31;
    int wm = wid & 3, wn = wid >> 2;
    int crow = blockIdx.y * 128, ccol = blockIdx.x * 128;

    float acc[2][8][4];
    #pragma unroll
    for (int a = 0; a < 2; a++)
        #pragma unroll
        for (int b = 0; b < 8; b++)
            #pragma unroll
            for (int c = 0; c < 4; c++) acc[a][b][c] = 0.f;

    gemm_load_stage(A, B, crow, ccol, 0, smb, tid);
    CP_COMMIT();

    for (int ch = 0; ch < 32; ch++) {
        int s = ch & 1;
        if (ch < 31) {
            gemm_load_stage(A, B, crow, ccol, ch + 1, smb + (s ^ 1) * 16384, tid);
            CP_COMMIT();
            CP_WAIT1();
        } else {
            CP_WAIT0();
        }
        __syncthreads();

        uint32_t Abase = smb + s * 16384;
        uint32_t Bbase = Abase + 8192;

        #pragma unroll
        for (int kt = 0; kt < 2; kt++) {
            uint32_t ah[2][4];
            #pragma unroll
            for (int mt = 0; mt < 2; mt++) {
                uint32_t off = Abase + sw((uint32_t)(
                    (wm * 32 + mt * 16 + (lane & 15)) * 64 +
                    kt * 32 + (lane >> 4) * 16));
                ldsm4(ah[mt], off);
            }
            #pragma unroll
            for (int jp = 0; jp < 4; jp++) {
                uint32_t boff = Bbase + sw((uint32_t)(
                    (wn * 64 + jp * 16 + (lane >> 4) * 8 + (lane & 7)) * 64 +
                    kt * 32 + ((lane >> 3) & 1) * 16));
                uint32_t bh[4];
                ldsm4(bh, boff);
                #pragma unroll
                for (int mt = 0; mt < 2; mt++) {
                    mma16816(acc[mt][2*jp],   ah[mt], bh[0], bh[1]);
                    mma16816(acc[mt][2*jp+1], ah[mt], bh[2], bh[3]);
                }
            }
        }
        __syncthreads();
    }

    // epilogue
    int g = lane >> 2, t2 = (lane & 3) * 2;
    #pragma unroll
    for (int mt = 0; mt < 2; mt++) {
        int row0 = crow + wm * 32 + mt * 16 + g;
        #pragma unroll
        for (int j = 0; j < 8; j++) {
            int col = ccol + wn * 64 + j * 8 + t2;
            if (MODE == 0) {
                #pragma unroll
                for (int r = 0; r < 2; r++) {
                    int tok = row0 + r * 8;
                    float v0 = acc[mt][j][2*r], v1 = acc[mt][j][2*r+1];
                    int which = col >> 10, rem = col & 1023;
                    int h = rem >> 6, d = rem & 63;
                    __half* dst = (which == 0) ? g_q : (which == 1) ? g_k : g_v;
                    float sc = (which == 0) ? QSCALE : 1.f;
                    size_t off = ((size_t)((tok >> 11) * HEADS + h) * NSEQ +
                                  (tok & (NSEQ - 1))) * HD + d;
                    *(uint32_t*)(dst + off) = pack_f16(v0 * sc, v1 * sc);
                }
            } else {
                float b0 = bias[col], b1 = bias[col + 1];
                #pragma unroll
                for (int r = 0; r < 2; r++) {
                    size_t o = (size_t)(row0 + r * 8) * DIM + col;
                    float2 rr = *(const float2*)(resid + o);
                    float2 vv = { acc[mt][j][2*r] + b0 + rr.x,
                                  acc[mt][j][2*r+1] + b1 + rr.y };
                    *(float2*)(out + o) = vv;
                }
            }
        }
    }
}

// ---------------------------------------------------------------------------
// Flash attention on mma.sync fp16. CTA = 128 q x one (b,h); 8 warps.
// Smem: Q 16KB @0; stages: K@16384+s*16384, V = K+8192. Total 49152.
// ---------------------------------------------------------------------------
#define ASMEM 49152

__device__ __forceinline__ void kv_load_stage(
    const __half* kg, const __half* vg, int k0, uint32_t sbase, int tid) {
    #pragma unroll
    for (int half_ = 0; half_ < 2; half_++) {
        int i = tid + half_ * 256;
        int key = i >> 3, ck = i & 7;
        uint32_t d = sbase + sw((uint32_t)(key * 128 + ck * 16));
        size_t gsrc = (size_t)(k0 + key) * HD + ck * 8;
        CP16(d,        kg + gsrc);
        CP16(d + 8192, vg + gsrc);
    }
}

__global__ __launch_bounds__(256, 2) void attn_mma() {
    extern __shared__ char smc[];
    uint32_t smb = smem_u32(smc);
    int tid = threadIdx.x, wid = tid >> 5, lane = tid & 31;
    int bh = blockIdx.y;
    int q0 = blockIdx.x * 128;

    const __half* qg = g_q + (size_t)bh * NSEQ * HD;
    const __half* kg = g_k + (size_t)bh * NSEQ * HD;
    const __half* vg = g_v + (size_t)bh * NSEQ * HD;

    // stage Q (128x64 fp16, swizzled)
    #pragma unroll
    for (int it = 0; it < 4; it++) {
        int i = tid * 4 + it;
        int row = i >> 3, ck = i & 7;
        uint4 val = *(const uint4*)(qg + (size_t)(q0 + row) * HD + ck * 8);
        *(uint4*)(smc + sw((uint32_t)(row * 128 + ck * 16))) = val;
    }
    __syncthreads();

    uint32_t qa[4][4];
    #pragma unroll
    for (int kt = 0; kt < 4; kt++) {
        uint32_t off = smb + sw((uint32_t)(
            (wid * 16 + (lane & 15)) * 128 + kt * 32 + (lane >> 4) * 16));
        ldsm4(qa[kt], off);
    }

    float o[8][4];
    #pragma unroll
    for (int j = 0; j < 8; j++)
        #pragma unroll
        for (int c = 0; c < 4; c++) o[j][c] = 0.f;
    float m0 = -1e30f, m1 = -1e30f, l0 = 0.f, l1 = 0.f;

    kv_load_stage(kg, vg, 0, smb + 16384, tid);
    CP_COMMIT();

    for (int t = 0; t < NSEQ / 64; t++) {
        int s = t & 1;
        if (t < NSEQ / 64 - 1) {
            kv_load_stage(kg, vg, (t + 1) * 64, smb + 16384 + (s ^ 1) * 16384, tid);
            CP_COMMIT();
            CP_WAIT1();
        } else {
            CP_WAIT0();
        }
        __syncthreads();

        uint32_t Kb = smb + 16384 + s * 16384;
        uint32_t Vb = Kb + 8192;

        // S = Q K^T
        float sc[8][4];
        #pragma unroll
        for (int j = 0; j < 8; j++)
            #pragma unroll
            for (int c = 0; c < 4; c++) sc[j][c] = 0.f;

        #pragma unroll
        for (int kt = 0; kt < 4; kt++) {
            #pragma unroll
            for (int jp = 0; jp < 4; jp++) {
                uint32_t r[4];
                uint32_t off = Kb + sw((uint32_t)(
                    (jp * 16 + (lane >> 4) * 8 + (lane & 7)) * 128 +
                    kt * 32 + ((lane >> 3) & 1) * 16));
                ldsm4(r, off);
                mma16816(sc[2*jp],   qa[kt], r[0], r[1]);
                mma16816(sc[2*jp+1], qa[kt], r[2], r[3]);
            }
        }

        // online softmax (log2 domain; Q pre-scaled by 0.125*log2e)
        float mx0 = -1e30f, mx1 = -1e30f;
        #pragma unroll
        for (int j = 0; j < 8; j++) {
            mx0 = fmaxf(mx0, fmaxf(sc[j][0], sc[j][1]));
            mx1 = fmaxf(mx1, fmaxf(sc[j][2], sc[j][3]));
        }
        mx0 = fmaxf(mx0, __shfl_xor_sync(0xFFFFFFFFu, mx0, 1));
        mx0 = fmaxf(mx0, __shfl_xor_sync(0xFFFFFFFFu, mx0, 2));
        mx1 = fmaxf(mx1, __shfl_xor_sync(0xFFFFFFFFu, mx1, 1));
        mx1 = fmaxf(mx1, __shfl_xor_sync(0xFFFFFFFFu, mx1, 2));
        float mn0 = fmaxf(m0, mx0), mn1 = fmaxf(m1, mx1);
        float cr0 = ex2(m0 - mn0), cr1 = ex2(m1 - mn1);
        m0 = mn0; m1 = mn1;

        uint32_t pa[4][4];
        float sl0 = 0.f, sl1 = 0.f;
        #pragma unroll
        for (int j = 0; j < 8; j++) {
            float p0 = ex2(sc[j][0] - mn0), p1 = ex2(sc[j][1] - mn0);
            float p2 = ex2(sc[j][2] - mn1), p3 = ex2(sc[j][3] - mn1);
            sl0 += p0 + p1; sl1 += p2 + p3;
            int kt = j >> 1, hi = (j & 1) * 2;
            pa[kt][hi]     = pack_f16(p0, p1);
            pa[kt][hi + 1] = pack_f16(p2, p3);
        }
        l0 = l0 * cr0 + sl0;
        l1 = l1 * cr1 + sl1;
        #pragma unroll
        for (int j = 0; j < 8; j++) {
            o[j][0] *= cr0; o[j][1] *= cr0;
            o[j][2] *= cr1; o[j][3] *= cr1;
        }

        // O += P V
        #pragma unroll
        for (int kt = 0; kt < 4; kt++) {
            #pragma unroll
            for (int j2 = 0; j2 < 4; j2++) {
                uint32_t v[4];
                uint32_t off = Vb + sw((uint32_t)(
                    (kt * 16 + ((lane >> 3) & 1) * 8 + (lane & 7)) * 128 +
                    j2 * 32 + ((lane >> 4) & 1) * 16));
                ldsm4t(v, off);
                mma16816(o[2*j2],   pa[kt], v[0], v[1]);
                mma16816(o[2*j2+1], pa[kt], v[2], v[3]);
            }
        }
        __syncthreads();
    }

    // epilogue
    l0 += __shfl_xor_sync(0xFFFFFFFFu, l0, 1);
    l0 += __shfl_xor_sync(0xFFFFFFFFu, l0, 2);
    l1 += __shfl_xor_sync(0xFFFFFFFFu, l1, 1);
    l1 += __shfl_xor_sync(0xFFFFFFFFu, l1, 2);
    float inv0 = 1.f / l0, inv1 = 1.f / l1;

    int b = bh >> 4, h = bh & 15;
    int n0 = q0 + wid * 16 + (lane >> 2);
    size_t t0 = (size_t)(b * NSEQ + n0) * DIM + h * HD;
    size_t t1 = t0 + (size_t)8 * DIM;
    #pragma unroll
    for (int j = 0; j < 8; j++) {
        int d = j * 8 + (lane & 3) * 2;
        *(uint32_t*)(g_attn + t0 + d) = pack_f16(o[j][0] * inv0, o[j][1] * inv0);
        *(uint32_t*)(g_attn + t1 + d) = pack_f16(o[j][2] * inv1, o[j][3] * inv1);
    }
}

// ---------------------------------------------------------------------------
extern "C" void kernel_launch(void* const* d_in, const int* in_sizes, int n_in,
                              void* d_out, int out_size) {
    const float* x      = (const float*)d_in[0];
    const float* w_qkv  = (const float*)d_in[1];
    const float* w_proj = (const float*)d_in[2];
    const float* b_proj = (const float*)d_in[3];
    const float* gamma  = (const float*)d_in[4];
    const float* beta   = (const float*)d_in[5];
    float* out = (float*)d_out;

    cudaFuncSetAttribute(gemm_mma<0>, cudaFuncAttributeMaxDynamicSharedMemorySize, GSMEM);
    cudaFuncSetAttribute(gemm_mma<1>, cudaFuncAttributeMaxDynamicSharedMemorySize, GSMEM);
    cudaFuncSetAttribute(attn_mma,    cudaFuncAttributeMaxDynamicSharedMemorySize, ASMEM);

    __half *lnp, *wqp, *wpp, *atp;
    cudaGetSymbolAddress((void**)&lnp, g_ln);
    cudaGetSymbolAddress((void**)&wqp, g_wqkvT);
    cudaGetSymbolAddress((void**)&wpp, g_wprojT);
    cudaGetSymbolAddress((void**)&atp, g_attn);

    // 1. LayerNorm -> fp16
    ln_kernel<<<TOKENS, 256>>>(x, gamma, beta);

    // 2. weight transpose -> [N][K] fp16
    wt_transpose<<<dim3(C3 / 32, DIM / 32), dim3(32, 8)>>>(w_qkv, wqp, DIM, C3);
    wt_transpose<<<dim3(DIM / 32, DIM / 32), dim3(32, 8)>>>(w_proj, wpp, DIM, DIM);

    // 3. QKV GEMM -> scatter fp16 q/k/v (q pre-scaled)
    gemm_mma<0><<<dim3(C3 / 128, TOKENS / 128), 256, GSMEM>>>(
        lnp, wqp, nullptr, nullptr, nullptr);

    // 4. attention -> fp16 [token][1024]
    attn_mma<<<dim3(NSEQ / 128, BATCH * HEADS), 256, ASMEM>>>();

    // 5. proj GEMM + bias + residual -> d_out
    gemm_mma<1><<<dim3(DIM / 128, TOKENS / 128), 256, GSMEM>>>(
        atp, wpp, out, b_proj, x);
}